// round 5
// baseline (speedup 1.0000x reference)
#include <cuda_runtime.h>
#include <cuda_bf16.h>
#include <math.h>

// ---------------------------------------------------------------------------
// Problem constants
// ---------------------------------------------------------------------------
#define HID   2048
#define NHEAD 32
#define HDIM  64
#define ROT   16
#define DFF   8192
#define SEQ   1024
#define BATCH 2
#define NTOK  (BATCH * SEQ)          // 2048 tokens

// ---------------------------------------------------------------------------
// Scratch (device globals; no allocations allowed)
// ---------------------------------------------------------------------------
__device__ float g_xln [NTOK * HID];
__device__ float g_q   [NTOK * HID];
__device__ float g_k   [NTOK * HID];
__device__ float g_v   [NTOK * HID];
__device__ float g_ctx [NTOK * HID];
__device__ float g_h   [NTOK * HID];
__device__ float g_y   [NTOK * HID];
__device__ float g_gate[(size_t)NTOK * DFF];
__device__ float g_up  [(size_t)NTOK * DFF];

// ---------------------------------------------------------------------------
// LayerNorm: one block per row of 2048
// ---------------------------------------------------------------------------
__global__ __launch_bounds__(256) void layernorm_k(
    const float* __restrict__ X, const float* __restrict__ w,
    const float* __restrict__ b, float* __restrict__ Y)
{
    const int row = blockIdx.x;
    const float* x = X + (size_t)row * HID;
    float sum = 0.f, sq = 0.f;
    for (int c = threadIdx.x * 4; c < HID; c += 256 * 4) {
        float4 v = *(const float4*)(x + c);
        sum += v.x + v.y + v.z + v.w;
        sq  += v.x * v.x + v.y * v.y + v.z * v.z + v.w * v.w;
    }
    __shared__ float s1[8], s2[8];
    #pragma unroll
    for (int o = 16; o > 0; o >>= 1) {
        sum += __shfl_xor_sync(0xffffffffu, sum, o);
        sq  += __shfl_xor_sync(0xffffffffu, sq, o);
    }
    if ((threadIdx.x & 31) == 0) { s1[threadIdx.x >> 5] = sum; s2[threadIdx.x >> 5] = sq; }
    __syncthreads();
    if (threadIdx.x < 32) {
        sum = (threadIdx.x < 8) ? s1[threadIdx.x] : 0.f;
        sq  = (threadIdx.x < 8) ? s2[threadIdx.x] : 0.f;
        #pragma unroll
        for (int o = 4; o > 0; o >>= 1) {
            sum += __shfl_xor_sync(0xffffffffu, sum, o);
            sq  += __shfl_xor_sync(0xffffffffu, sq, o);
        }
        if (threadIdx.x == 0) { s1[0] = sum; s2[0] = sq; }
    }
    __syncthreads();
    const float mean = s1[0] * (1.f / HID);
    const float var  = s2[0] * (1.f / HID) - mean * mean;
    const float rstd = rsqrtf(var + 1e-5f);
    float* y = Y + (size_t)row * HID;
    for (int c = threadIdx.x * 4; c < HID; c += 256 * 4) {
        float4 v  = *(const float4*)(x + c);
        float4 wv = *(const float4*)(w + c);
        float4 bv = *(const float4*)(b + c);
        float4 o;
        o.x = (v.x - mean) * rstd * wv.x + bv.x;
        o.y = (v.y - mean) * rstd * wv.y + bv.y;
        o.z = (v.z - mean) * rstd * wv.z + bv.z;
        o.w = (v.w - mean) * rstd * wv.w + bv.w;
        *(float4*)(y + c) = o;
    }
}

// ---------------------------------------------------------------------------
// NT SGEMM:  C[M,N] = A[M,K] * B[N,K]^T  (+ Cin)     both operands K-major
// 128x128 tile, BK=8, 8x8 per thread, 256 threads, float4 everywhere.
// All dims divisible by 128/8 in this problem -> no bounds checks.
// ---------------------------------------------------------------------------
#define GBM 128
#define GBN 128
#define GBK 8
#define GTM 8
#define GTN 8

__global__ __launch_bounds__(256) void sgemm_nt(
    const float* __restrict__ A, const float* __restrict__ B,
    const float* __restrict__ Cin, float* __restrict__ C,
    int M, int N, int K)
{
    __shared__ float As[GBK][GBM];
    __shared__ float Bs[GBK][GBN];

    const int tid = threadIdx.x;
    const int bx = blockIdx.x, by = blockIdx.y;
    const int threadRow = tid / 16;          // 0..15
    const int threadCol = tid % 16;          // 0..15
    const int innerRow  = tid / 2;           // 0..127
    const int innerCol  = (tid % 2) * 4;     // 0 or 4

    const float* Ab = A + (size_t)(by * GBM) * K;
    const float* Bb = B + (size_t)(bx * GBN) * K;

    float acc[GTM][GTN] = {};
    float regM[GTM], regN[GTN];

    for (int k0 = 0; k0 < K; k0 += GBK) {
        float4 a4 = *(const float4*)(Ab + (size_t)innerRow * K + k0 + innerCol);
        float4 b4 = *(const float4*)(Bb + (size_t)innerRow * K + k0 + innerCol);
        As[innerCol + 0][innerRow] = a4.x;
        As[innerCol + 1][innerRow] = a4.y;
        As[innerCol + 2][innerRow] = a4.z;
        As[innerCol + 3][innerRow] = a4.w;
        Bs[innerCol + 0][innerRow] = b4.x;
        Bs[innerCol + 1][innerRow] = b4.y;
        Bs[innerCol + 2][innerRow] = b4.z;
        Bs[innerCol + 3][innerRow] = b4.w;
        __syncthreads();
        #pragma unroll
        for (int k = 0; k < GBK; k++) {
            #pragma unroll
            for (int i = 0; i < GTM; i++) regM[i] = As[k][threadRow * GTM + i];
            #pragma unroll
            for (int j = 0; j < GTN; j++) regN[j] = Bs[k][threadCol * GTN + j];
            #pragma unroll
            for (int i = 0; i < GTM; i++)
                #pragma unroll
                for (int j = 0; j < GTN; j++)
                    acc[i][j] += regM[i] * regN[j];
        }
        __syncthreads();
    }

    #pragma unroll
    for (int i = 0; i < GTM; i++) {
        const int row = by * GBM + threadRow * GTM + i;
        float* Crow = C + (size_t)row * N + bx * GBN + threadCol * GTN;
        #pragma unroll
        for (int j = 0; j < GTN; j += 4) {
            float4 v = make_float4(acc[i][j], acc[i][j + 1], acc[i][j + 2], acc[i][j + 3]);
            if (Cin) {
                const float4 c = *(const float4*)(Cin + (size_t)row * N + bx * GBN + threadCol * GTN + j);
                v.x += c.x; v.y += c.y; v.z += c.z; v.w += c.w;
            }
            *(float4*)(Crow + j) = v;
        }
    }
}

// ---------------------------------------------------------------------------
// RoPE in-place on q and k (first ROT=16 dims per head).
// One thread per (token, head, d<8) pair.
// ---------------------------------------------------------------------------
__global__ void rope_k(float* __restrict__ q, float* __restrict__ k,
                       const int* __restrict__ pos_ids)
{
    const int idx = blockIdx.x * blockDim.x + threadIdx.x;
    const int total = NTOK * NHEAD * 8;
    if (idx >= total) return;
    const int d   = idx & 7;
    const int h   = (idx >> 3) & (NHEAD - 1);
    const int tkn = idx >> 8;                 // 8*32 = 256 per token
    const float pos = (float)pos_ids[tkn];
    // inv_freq = ROPE_BASE^(-(2d)/ROT) = 10000^(-d/8)
    const float inv = powf(10000.f, -(float)d * 0.125f);
    float s, c;
    sincosf(pos * inv, &s, &c);
    const size_t base = (size_t)tkn * HID + h * HDIM;
    {
        const float x0 = q[base + d], x1 = q[base + d + 8];
        q[base + d]     = x0 * c - x1 * s;
        q[base + d + 8] = x1 * c + x0 * s;
    }
    {
        const float x0 = k[base + d], x1 = k[base + d + 8];
        k[base + d]     = x0 * c - x1 * s;
        k[base + d + 8] = x1 * c + x0 * s;
    }
}

// ---------------------------------------------------------------------------
// Flash attention: grid (S/64, H, B), 256 threads.
// 64x64 Q tile, 64 kv per iteration, online softmax.
// smem: Qs | Ks | Vs (48 KB); P tile aliases Ks after score phase.
// Thread mapping: r = tid/4 (q-row), part = tid%4 owns 16 of 64 cols/dims.
// ---------------------------------------------------------------------------
__global__ __launch_bounds__(256) void attn_k(
    const float* __restrict__ Q, const float* __restrict__ K,
    const float* __restrict__ V, const float* __restrict__ mask,
    float* __restrict__ O)
{
    __shared__ float sm[3 * 64 * 64];
    float* Qs = sm;
    float* Ks = sm + 4096;
    float* Vs = sm + 8192;
    float* Ps = Ks;          // aliased: Ks is dead once scores are in registers

    const int qt = blockIdx.x, h = blockIdx.y, b = blockIdx.z;
    const int tid  = threadIdx.x;
    const int r    = tid >> 2;       // q row within tile
    const int part = tid & 3;
    const int d0   = part * 16;

    const size_t qbase = ((size_t)(b * SEQ + qt * 64) * HID) + h * HDIM;

    // load Q tile, pre-scaled by 1/sqrt(64)
    for (int i = tid; i < 64 * 16; i += 256) {
        const int row = i >> 4, c4 = (i & 15) * 4;
        float4 v = *(const float4*)(Q + qbase + (size_t)row * HID + c4);
        v.x *= 0.125f; v.y *= 0.125f; v.z *= 0.125f; v.w *= 0.125f;
        *(float4*)(Qs + row * 64 + c4) = v;
    }

    float acc[16] = {};
    float mrun = -1e30f, lrun = 0.f;
    const float* maskrow = mask + (size_t)b * SEQ * SEQ + (size_t)(qt * 64 + r) * SEQ;

    for (int t = 0; t < SEQ / 64; t++) {
        __syncthreads();  // previous P/V reads complete before overwrite
        const size_t kvb = ((size_t)(b * SEQ + t * 64) * HID) + h * HDIM;
        for (int i = tid; i < 64 * 16; i += 256) {
            const int row = i >> 4, c4 = (i & 15) * 4;
            *(float4*)(Ks + row * 64 + c4) = *(const float4*)(K + kvb + (size_t)row * HID + c4);
            *(float4*)(Vs + row * 64 + c4) = *(const float4*)(V + kvb + (size_t)row * HID + c4);
        }
        __syncthreads();

        // scores for this thread's 16 columns
        float sc[16];
        const float4* qrow = (const float4*)(Qs + r * 64);
        #pragma unroll
        for (int jj = 0; jj < 16; jj++) {
            const int j = d0 + jj;
            const float4* krow = (const float4*)(Ks + j * 64);
            float s = 0.f;
            #pragma unroll
            for (int d4 = 0; d4 < 16; d4++) {
                const float4 a = qrow[d4], bb = krow[d4];
                s += a.x * bb.x + a.y * bb.y + a.z * bb.z + a.w * bb.w;
            }
            sc[jj] = s + maskrow[t * 64 + j];
        }

        // row max across the 4 threads of this row
        float mt = sc[0];
        #pragma unroll
        for (int jj = 1; jj < 16; jj++) mt = fmaxf(mt, sc[jj]);
        mt = fmaxf(mt, __shfl_xor_sync(0xffffffffu, mt, 1));
        mt = fmaxf(mt, __shfl_xor_sync(0xffffffffu, mt, 2));
        const float mnew  = fmaxf(mrun, mt);
        const float scale = __expf(mrun - mnew);

        float lsum = 0.f;
        #pragma unroll
        for (int jj = 0; jj < 16; jj++) { sc[jj] = __expf(sc[jj] - mnew); lsum += sc[jj]; }
        lsum += __shfl_xor_sync(0xffffffffu, lsum, 1);
        lsum += __shfl_xor_sync(0xffffffffu, lsum, 2);
        lrun = lrun * scale + lsum;
        mrun = mnew;
        #pragma unroll
        for (int dd = 0; dd < 16; dd++) acc[dd] *= scale;

        __syncthreads();  // all Ks reads done -> safe to write Ps (alias)
        #pragma unroll
        for (int jj = 0; jj < 16; jj++) Ps[r * 64 + d0 + jj] = sc[jj];
        __syncthreads();

        // O += P @ V on this thread's 16 output dims
        #pragma unroll
        for (int j = 0; j < 64; j++) {
            const float pv = Ps[r * 64 + j];
            const float4* vrow = (const float4*)(Vs + j * 64 + d0);
            #pragma unroll
            for (int q4 = 0; q4 < 4; q4++) {
                const float4 v = vrow[q4];
                acc[q4 * 4 + 0] += pv * v.x;
                acc[q4 * 4 + 1] += pv * v.y;
                acc[q4 * 4 + 2] += pv * v.z;
                acc[q4 * 4 + 3] += pv * v.w;
            }
        }
    }

    const float inv_l = 1.f / lrun;
    float* orow = O + qbase + (size_t)r * HID + d0;
    #pragma unroll
    for (int dd = 0; dd < 16; dd += 4) {
        float4 v = make_float4(acc[dd] * inv_l, acc[dd + 1] * inv_l,
                               acc[dd + 2] * inv_l, acc[dd + 3] * inv_l);
        *(float4*)(orow + dd) = v;
    }
}

// ---------------------------------------------------------------------------
// act = silu(gate) * up, written in place into gate buffer
// ---------------------------------------------------------------------------
__global__ void silu_mul_k(float* __restrict__ g, const float* __restrict__ u, int n4)
{
    const int i = blockIdx.x * blockDim.x + threadIdx.x;
    if (i >= n4) return;
    float4 gv = *(float4*)(g + (size_t)i * 4);
    const float4 uv = *(const float4*)(u + (size_t)i * 4);
    gv.x = gv.x / (1.f + __expf(-gv.x)) * uv.x;
    gv.y = gv.y / (1.f + __expf(-gv.y)) * uv.y;
    gv.z = gv.z / (1.f + __expf(-gv.z)) * uv.z;
    gv.w = gv.w / (1.f + __expf(-gv.w)) * uv.w;
    *(float4*)(g + (size_t)i * 4) = gv;
}

// ---------------------------------------------------------------------------
// Orchestration
// ---------------------------------------------------------------------------
extern "C" void kernel_launch(void* const* d_in, const int* in_sizes, int n_in,
                              void* d_out, int out_size)
{
    const float* hid   = (const float*)d_in[0];
    const float* mem   = (const float*)d_in[1];
    const float* mask  = (const float*)d_in[2];
    const int*   pos   = (const int*)  d_in[3];
    const float* Wq    = (const float*)d_in[4];
    const float* Wk    = (const float*)d_in[5];
    const float* Wv    = (const float*)d_in[6];
    const float* Wo    = (const float*)d_in[7];
    const float* ln1w  = (const float*)d_in[8];
    const float* ln1b  = (const float*)d_in[9];
    const float* ln2w  = (const float*)d_in[10];
    const float* ln2b  = (const float*)d_in[11];
    const float* gatew = (const float*)d_in[12];
    const float* upw   = (const float*)d_in[13];
    const float* downw = (const float*)d_in[14];
    float* out = (float*)d_out;

    float *xln, *q, *k, *v, *ctx, *h, *y, *gg, *uu;
    cudaGetSymbolAddress((void**)&xln, g_xln);
    cudaGetSymbolAddress((void**)&q,   g_q);
    cudaGetSymbolAddress((void**)&k,   g_k);
    cudaGetSymbolAddress((void**)&v,   g_v);
    cudaGetSymbolAddress((void**)&ctx, g_ctx);
    cudaGetSymbolAddress((void**)&h,   g_h);
    cudaGetSymbolAddress((void**)&y,   g_y);
    cudaGetSymbolAddress((void**)&gg,  g_gate);
    cudaGetSymbolAddress((void**)&uu,  g_up);

    // 1. ln1
    layernorm_k<<<NTOK, 256>>>(hid, ln1w, ln1b, xln);

    // 2-4. Q/K/V projections (NT GEMMs)
    dim3 gsq(HID / GBN, NTOK / GBM);
    sgemm_nt<<<gsq, 256>>>(xln, Wq, nullptr, q, NTOK, HID, HID);
    sgemm_nt<<<gsq, 256>>>(mem, Wk, nullptr, k, NTOK, HID, HID);
    sgemm_nt<<<gsq, 256>>>(mem, Wv, nullptr, v, NTOK, HID, HID);

    // 5. RoPE (in place)
    const int rope_threads = NTOK * NHEAD * 8;
    rope_k<<<(rope_threads + 255) / 256, 256>>>(q, k, pos);

    // 6. Attention -> ctx
    dim3 ga(SEQ / 64, NHEAD, BATCH);
    attn_k<<<ga, 256>>>(q, k, v, mask, ctx);

    // 7. O projection + residual
    sgemm_nt<<<gsq, 256>>>(ctx, Wo, hid, h, NTOK, HID, HID);

    // 8. ln2
    layernorm_k<<<NTOK, 256>>>(h, ln2w, ln2b, y);

    // 9-10. gate / up
    dim3 gff(DFF / GBN, NTOK / GBM);
    sgemm_nt<<<gff, 256>>>(y, gatew, nullptr, gg, NTOK, DFF, HID);
    sgemm_nt<<<gff, 256>>>(y, upw,   nullptr, uu, NTOK, DFF, HID);

    // 11. silu(gate) * up  (in place into gg)
    const int n4 = (NTOK * DFF) / 4;
    silu_mul_k<<<(n4 + 255) / 256, 256>>>(gg, uu, n4);

    // 12. down projection + residual -> out
    sgemm_nt<<<gsq, 256>>>(gg, downw, h, out, NTOK, HID, DFF);
}

// round 10
// speedup vs baseline: 1.9854x; 1.9854x over previous
#include <cuda_runtime.h>
#include <cuda_bf16.h>
#include <cstdint>
#include <math.h>

// ---------------------------------------------------------------------------
// Problem constants
// ---------------------------------------------------------------------------
#define HID   2048
#define NHEAD 32
#define HDIM  64
#define DFF   8192
#define SEQ   1024
#define BATCH 2
#define NTOK  (BATCH * SEQ)          // 2048 tokens

// ---------------------------------------------------------------------------
// Scratch (device globals; no allocations allowed)
// ---------------------------------------------------------------------------
__device__ float g_xln [NTOK * HID];
__device__ float g_q   [NTOK * HID];
__device__ float g_k   [NTOK * HID];
__device__ float g_v   [NTOK * HID];
__device__ float g_ctx [NTOK * HID];
__device__ float g_h   [NTOK * HID];
__device__ float g_y   [NTOK * HID];
__device__ float g_gate[(size_t)NTOK * DFF];
__device__ float g_up  [(size_t)NTOK * DFF];
// tf32-rounded copies of GEMM B-operands (weights) and memory activation
__device__ float g_memr[NTOK * HID];
__device__ float g_wq  [HID * HID];
__device__ float g_wk  [HID * HID];
__device__ float g_wv  [HID * HID];
__device__ float g_wo  [HID * HID];
__device__ float g_gw  [(size_t)DFF * HID];
__device__ float g_uw  [(size_t)DFF * HID];
__device__ float g_dw  [(size_t)HID * DFF];

// ---------------------------------------------------------------------------
// Helpers
// ---------------------------------------------------------------------------
__device__ __forceinline__ uint32_t smem_u32(const void* p) {
    uint32_t a;
    asm("{ .reg .u64 t; cvta.to.shared.u64 t, %1; cvt.u32.u64 %0, t; }"
        : "=r"(a) : "l"(p));
    return a;
}

__device__ __forceinline__ float rtf32(float x) {
    float r;
    asm("cvt.rna.tf32.f32 %0, %1;" : "=f"(r) : "f"(x));
    return r;
}

__device__ __forceinline__ void cp16(uint32_t s, const void* g) {
    asm volatile("cp.async.cg.shared.global [%0], [%1], 16;" :: "r"(s), "l"(g));
}
#define CP_COMMIT() asm volatile("cp.async.commit_group;" ::: "memory")
#define CP_WAIT1()  asm volatile("cp.async.wait_group 1;" ::: "memory")
#define CP_WAIT0()  asm volatile("cp.async.wait_group 0;" ::: "memory")

// m16n8k8 tf32 tensor-core mma (family-target PTX, sm_80+)
__device__ __forceinline__ void mma_tf32(float* c, const uint32_t* a, const uint32_t* b) {
    asm volatile(
        "mma.sync.aligned.m16n8k8.row.col.f32.tf32.tf32.f32 "
        "{%0,%1,%2,%3}, {%4,%5,%6,%7}, {%8,%9}, {%0,%1,%2,%3};"
        : "+f"(c[0]), "+f"(c[1]), "+f"(c[2]), "+f"(c[3])
        : "r"(a[0]), "r"(a[1]), "r"(a[2]), "r"(a[3]), "r"(b[0]), "r"(b[1]));
}

// ---------------------------------------------------------------------------
// Elementwise tf32 rounding pass (weights + memory operand)
// ---------------------------------------------------------------------------
__global__ void round_tf32_k(const float* __restrict__ x, float* __restrict__ y, int n4)
{
    const int i = blockIdx.x * blockDim.x + threadIdx.x;
    if (i >= n4) return;
    float4 v = ((const float4*)x)[i];
    v.x = rtf32(v.x); v.y = rtf32(v.y); v.z = rtf32(v.z); v.w = rtf32(v.w);
    ((float4*)y)[i] = v;
}

// ---------------------------------------------------------------------------
// LayerNorm: one block per row; output rounded to tf32 (feeds GEMM A-operand)
// ---------------------------------------------------------------------------
__global__ __launch_bounds__(256) void layernorm_k(
    const float* __restrict__ X, const float* __restrict__ w,
    const float* __restrict__ b, float* __restrict__ Y)
{
    const int row = blockIdx.x;
    const float* x = X + (size_t)row * HID;
    float sum = 0.f, sq = 0.f;
    for (int c = threadIdx.x * 4; c < HID; c += 256 * 4) {
        float4 v = *(const float4*)(x + c);
        sum += v.x + v.y + v.z + v.w;
        sq  += v.x * v.x + v.y * v.y + v.z * v.z + v.w * v.w;
    }
    __shared__ float s1[8], s2[8];
    #pragma unroll
    for (int o = 16; o > 0; o >>= 1) {
        sum += __shfl_xor_sync(0xffffffffu, sum, o);
        sq  += __shfl_xor_sync(0xffffffffu, sq, o);
    }
    if ((threadIdx.x & 31) == 0) { s1[threadIdx.x >> 5] = sum; s2[threadIdx.x >> 5] = sq; }
    __syncthreads();
    if (threadIdx.x < 32) {
        sum = (threadIdx.x < 8) ? s1[threadIdx.x] : 0.f;
        sq  = (threadIdx.x < 8) ? s2[threadIdx.x] : 0.f;
        #pragma unroll
        for (int o = 4; o > 0; o >>= 1) {
            sum += __shfl_xor_sync(0xffffffffu, sum, o);
            sq  += __shfl_xor_sync(0xffffffffu, sq, o);
        }
        if (threadIdx.x == 0) { s1[0] = sum; s2[0] = sq; }
    }
    __syncthreads();
    const float mean = s1[0] * (1.f / HID);
    const float var  = s2[0] * (1.f / HID) - mean * mean;
    const float rstd = rsqrtf(var + 1e-5f);
    float* y = Y + (size_t)row * HID;
    for (int c = threadIdx.x * 4; c < HID; c += 256 * 4) {
        float4 v  = *(const float4*)(x + c);
        float4 wv = *(const float4*)(w + c);
        float4 bv = *(const float4*)(b + c);
        float4 o;
        o.x = rtf32((v.x - mean) * rstd * wv.x + bv.x);
        o.y = rtf32((v.y - mean) * rstd * wv.y + bv.y);
        o.z = rtf32((v.z - mean) * rstd * wv.z + bv.z);
        o.w = rtf32((v.w - mean) * rstd * wv.w + bv.w);
        *(float4*)(y + c) = o;
    }
}

// ---------------------------------------------------------------------------
// TF32 tensor-core NT GEMM via mma.sync:  C[M,N] = A[M,K]*B[N,K]^T (+ Cin)
// CTA 128x128, BK=16, 256 threads (8 warps = 2x4), warp tile 64x32.
// Double-buffered cp.async. smem [row][BK+4] padding -> conflict-free.
// M%128==0, N%128==0, K%16==0 for all calls here.
// ---------------------------------------------------------------------------
#define GM 128
#define GN 128
#define GK 16
#define LDS_K 20                      // GK + 4 pad
#define STG_F (GM * LDS_K)            // floats per stage buffer (2560)

__device__ __forceinline__ void load_stage(
    int tid, const float* Ag, const float* Bg, int K, int k0,
    uint32_t sA, uint32_t sB)
{
    #pragma unroll
    for (int t = 0; t < 2; t++) {
        const int idx = tid + t * 256;
        const int row = idx >> 2, c4 = idx & 3;
        cp16(sA + (uint32_t)(row * LDS_K + c4 * 4) * 4, Ag + (size_t)row * K + k0 + c4 * 4);
    }
    #pragma unroll
    for (int t = 0; t < 2; t++) {
        const int idx = tid + t * 256;
        const int row = idx >> 2, c4 = idx & 3;
        cp16(sB + (uint32_t)(row * LDS_K + c4 * 4) * 4, Bg + (size_t)row * K + k0 + c4 * 4);
    }
    CP_COMMIT();
}

__global__ __launch_bounds__(256) void gemm_mma(
    const float* __restrict__ A, const float* __restrict__ B,
    const float* __restrict__ Cin, float* __restrict__ C,
    int M, int N, int K)
{
    __shared__ float smA[2][STG_F];
    __shared__ float smB[2][STG_F];

    const int tid  = threadIdx.x;
    const int wid  = tid >> 5;
    const int lane = tid & 31;
    const int wm   = wid & 1;          // warp m index (0..1)
    const int wn   = wid >> 1;         // warp n index (0..3)
    const int m0   = blockIdx.y * GM;
    const int n0   = blockIdx.x * GN;

    const float* Ag = A + (size_t)m0 * K;
    const float* Bg = B + (size_t)n0 * K;

    const uint32_t sA0 = smem_u32(smA[0]), sA1 = smem_u32(smA[1]);
    const uint32_t sB0 = smem_u32(smB[0]), sB1 = smem_u32(smB[1]);

    float acc[4][4][4] = {};   // [mf][nf][reg]

    const int S = K / GK;
    load_stage(tid, Ag, Bg, K, 0,  sA0, sB0);
    load_stage(tid, Ag, Bg, K, GK, sA1, sB1);

    const int lr = lane >> 2;          // 0..7
    const int lc = lane & 3;           // 0..3

    for (int s = 0; s < S; s++) {
        const int b = s & 1;
        CP_WAIT1();
        __syncthreads();
        const float* As = smA[b];
        const float* Bs = smB[b];

        #pragma unroll
        for (int ks = 0; ks < 2; ks++) {
            const int k0 = ks * 8;
            uint32_t af[4][4];
            #pragma unroll
            for (int mf = 0; mf < 4; mf++) {
                const float* ap = As + (wm * 64 + mf * 16 + lr) * LDS_K + k0 + lc;
                af[mf][0] = __float_as_uint(ap[0]);
                af[mf][1] = __float_as_uint(ap[8 * LDS_K]);
                af[mf][2] = __float_as_uint(ap[4]);
                af[mf][3] = __float_as_uint(ap[8 * LDS_K + 4]);
            }
            uint32_t bf[4][2];
            #pragma unroll
            for (int nf = 0; nf < 4; nf++) {
                const float* bp = Bs + (wn * 32 + nf * 8 + lr) * LDS_K + k0 + lc;
                bf[nf][0] = __float_as_uint(bp[0]);
                bf[nf][1] = __float_as_uint(bp[4]);
            }
            #pragma unroll
            for (int mf = 0; mf < 4; mf++)
                #pragma unroll
                for (int nf = 0; nf < 4; nf++)
                    mma_tf32(acc[mf][nf], af[mf], bf[nf]);
        }
        __syncthreads();
        if (s + 2 < S)
            load_stage(tid, Ag, Bg, K, (s + 2) * GK,
                       b ? sA1 : sA0, b ? sB1 : sB0);
    }
    CP_WAIT0();

    // epilogue: frag (mf,nf): rows m0+wm*64+mf*16+{lr, lr+8}, cols n0+wn*32+nf*8+2*lc
    #pragma unroll
    for (int mf = 0; mf < 4; mf++) {
        const int r0 = m0 + wm * 64 + mf * 16 + lr;
        #pragma unroll
        for (int nf = 0; nf < 4; nf++) {
            const int c0 = n0 + wn * 32 + nf * 8 + 2 * lc;
            float2 v0 = make_float2(acc[mf][nf][0], acc[mf][nf][1]);
            float2 v1 = make_float2(acc[mf][nf][2], acc[mf][nf][3]);
            if (Cin) {
                const float2 p0 = *(const float2*)(Cin + (size_t)r0 * N + c0);
                const float2 p1 = *(const float2*)(Cin + (size_t)(r0 + 8) * N + c0);
                v0.x += p0.x; v0.y += p0.y;
                v1.x += p1.x; v1.y += p1.y;
            }
            *(float2*)(C + (size_t)r0 * N + c0)       = v0;
            *(float2*)(C + (size_t)(r0 + 8) * N + c0) = v1;
        }
    }
}

// ---------------------------------------------------------------------------
// RoPE in-place on q and k (first 16 dims per head).
// ---------------------------------------------------------------------------
__global__ void rope_k(float* __restrict__ q, float* __restrict__ k,
                       const int* __restrict__ pos_ids)
{
    const int idx = blockIdx.x * blockDim.x + threadIdx.x;
    const int total = NTOK * NHEAD * 8;
    if (idx >= total) return;
    const int d   = idx & 7;
    const int h   = (idx >> 3) & (NHEAD - 1);
    const int tkn = idx >> 8;
    const float pos = (float)pos_ids[tkn];
    const float inv = powf(10000.f, -(float)d * 0.125f);
    float s, c;
    sincosf(pos * inv, &s, &c);
    const size_t base = (size_t)tkn * HID + h * HDIM;
    {
        const float x0 = q[base + d], x1 = q[base + d + 8];
        q[base + d]     = x0 * c - x1 * s;
        q[base + d + 8] = x1 * c + x0 * s;
    }
    {
        const float x0 = k[base + d], x1 = k[base + d + 8];
        k[base + d]     = x0 * c - x1 * s;
        k[base + d + 8] = x1 * c + x0 * s;
    }
}

// ---------------------------------------------------------------------------
// Flash attention (fp32) — output rounded to tf32 (feeds Wo GEMM)
// ---------------------------------------------------------------------------
__global__ __launch_bounds__(256) void attn_k(
    const float* __restrict__ Q, const float* __restrict__ K,
    const float* __restrict__ V, const float* __restrict__ mask,
    float* __restrict__ O)
{
    __shared__ float sm[3 * 64 * 64];
    float* Qs = sm;
    float* Ks = sm + 4096;
    float* Vs = sm + 8192;
    float* Ps = Ks;

    const int qt = blockIdx.x, h = blockIdx.y, b = blockIdx.z;
    const int tid  = threadIdx.x;
    const int r    = tid >> 2;
    const int part = tid & 3;
    const int d0   = part * 16;

    const size_t qbase = ((size_t)(b * SEQ + qt * 64) * HID) + h * HDIM;

    for (int i = tid; i < 64 * 16; i += 256) {
        const int row = i >> 4, c4 = (i & 15) * 4;
        float4 v = *(const float4*)(Q + qbase + (size_t)row * HID + c4);
        v.x *= 0.125f; v.y *= 0.125f; v.z *= 0.125f; v.w *= 0.125f;
        *(float4*)(Qs + row * 64 + c4) = v;
    }

    float acc[16] = {};
    float mrun = -1e30f, lrun = 0.f;
    const float* maskrow = mask + (size_t)b * SEQ * SEQ + (size_t)(qt * 64 + r) * SEQ;

    for (int t = 0; t < SEQ / 64; t++) {
        __syncthreads();
        const size_t kvb = ((size_t)(b * SEQ + t * 64) * HID) + h * HDIM;
        for (int i = tid; i < 64 * 16; i += 256) {
            const int row = i >> 4, c4 = (i & 15) * 4;
            *(float4*)(Ks + row * 64 + c4) = *(const float4*)(K + kvb + (size_t)row * HID + c4);
            *(float4*)(Vs + row * 64 + c4) = *(const float4*)(V + kvb + (size_t)row * HID + c4);
        }
        __syncthreads();

        float sc[16];
        const float4* qrow = (const float4*)(Qs + r * 64);
        #pragma unroll
        for (int jj = 0; jj < 16; jj++) {
            const int j = d0 + jj;
            const float4* krow = (const float4*)(Ks + j * 64);
            float s = 0.f;
            #pragma unroll
            for (int d4 = 0; d4 < 16; d4++) {
                const float4 a = qrow[d4], bb = krow[d4];
                s += a.x * bb.x + a.y * bb.y + a.z * bb.z + a.w * bb.w;
            }
            sc[jj] = s + maskrow[t * 64 + j];
        }

        float mt = sc[0];
        #pragma unroll
        for (int jj = 1; jj < 16; jj++) mt = fmaxf(mt, sc[jj]);
        mt = fmaxf(mt, __shfl_xor_sync(0xffffffffu, mt, 1));
        mt = fmaxf(mt, __shfl_xor_sync(0xffffffffu, mt, 2));
        const float mnew  = fmaxf(mrun, mt);
        const float scale = __expf(mrun - mnew);

        float lsum = 0.f;
        #pragma unroll
        for (int jj = 0; jj < 16; jj++) { sc[jj] = __expf(sc[jj] - mnew); lsum += sc[jj]; }
        lsum += __shfl_xor_sync(0xffffffffu, lsum, 1);
        lsum += __shfl_xor_sync(0xffffffffu, lsum, 2);
        lrun = lrun * scale + lsum;
        mrun = mnew;
        #pragma unroll
        for (int dd = 0; dd < 16; dd++) acc[dd] *= scale;

        __syncthreads();
        #pragma unroll
        for (int jj = 0; jj < 16; jj++) Ps[r * 64 + d0 + jj] = sc[jj];
        __syncthreads();

        #pragma unroll
        for (int j = 0; j < 64; j++) {
            const float pv = Ps[r * 64 + j];
            const float4* vrow = (const float4*)(Vs + j * 64 + d0);
            #pragma unroll
            for (int q4 = 0; q4 < 4; q4++) {
                const float4 v = vrow[q4];
                acc[q4 * 4 + 0] += pv * v.x;
                acc[q4 * 4 + 1] += pv * v.y;
                acc[q4 * 4 + 2] += pv * v.z;
                acc[q4 * 4 + 3] += pv * v.w;
            }
        }
    }

    const float inv_l = 1.f / lrun;
    float* orow = O + qbase + (size_t)r * HID + d0;
    #pragma unroll
    for (int dd = 0; dd < 16; dd += 4) {
        float4 v = make_float4(rtf32(acc[dd] * inv_l),     rtf32(acc[dd + 1] * inv_l),
                               rtf32(acc[dd + 2] * inv_l), rtf32(acc[dd + 3] * inv_l));
        *(float4*)(orow + dd) = v;
    }
}

// ---------------------------------------------------------------------------
// act = silu(gate) * up (in place into gate), rounded to tf32
// ---------------------------------------------------------------------------
__global__ void silu_mul_k(float* __restrict__ g, const float* __restrict__ u, int n4)
{
    const int i = blockIdx.x * blockDim.x + threadIdx.x;
    if (i >= n4) return;
    float4 gv = *(float4*)(g + (size_t)i * 4);
    const float4 uv = *(const float4*)(u + (size_t)i * 4);
    gv.x = rtf32(gv.x / (1.f + __expf(-gv.x)) * uv.x);
    gv.y = rtf32(gv.y / (1.f + __expf(-gv.y)) * uv.y);
    gv.z = rtf32(gv.z / (1.f + __expf(-gv.z)) * uv.z);
    gv.w = rtf32(gv.w / (1.f + __expf(-gv.w)) * uv.w);
    *(float4*)(g + (size_t)i * 4) = gv;
}

// ---------------------------------------------------------------------------
// Orchestration
// ---------------------------------------------------------------------------
static inline void round_pass(const float* src, float* dst, size_t n)
{
    const int n4 = (int)(n / 4);
    round_tf32_k<<<(n4 + 255) / 256, 256>>>(src, dst, n4);
}

extern "C" void kernel_launch(void* const* d_in, const int* in_sizes, int n_in,
                              void* d_out, int out_size)
{
    const float* hid   = (const float*)d_in[0];
    const float* mem   = (const float*)d_in[1];
    const float* mask  = (const float*)d_in[2];
    const int*   pos   = (const int*)  d_in[3];
    const float* Wq    = (const float*)d_in[4];
    const float* Wk    = (const float*)d_in[5];
    const float* Wv    = (const float*)d_in[6];
    const float* Wo    = (const float*)d_in[7];
    const float* ln1w  = (const float*)d_in[8];
    const float* ln1b  = (const float*)d_in[9];
    const float* ln2w  = (const float*)d_in[10];
    const float* ln2b  = (const float*)d_in[11];
    const float* gatew = (const float*)d_in[12];
    const float* upw   = (const float*)d_in[13];
    const float* downw = (const float*)d_in[14];
    float* out = (float*)d_out;

    float *xln, *q, *k, *v, *ctx, *h, *y, *gg, *uu;
    float *memr, *wq, *wk, *wv, *wo, *gw, *uw, *dw;
    cudaGetSymbolAddress((void**)&xln, g_xln);
    cudaGetSymbolAddress((void**)&q,   g_q);
    cudaGetSymbolAddress((void**)&k,   g_k);
    cudaGetSymbolAddress((void**)&v,   g_v);
    cudaGetSymbolAddress((void**)&ctx, g_ctx);
    cudaGetSymbolAddress((void**)&h,   g_h);
    cudaGetSymbolAddress((void**)&y,   g_y);
    cudaGetSymbolAddress((void**)&gg,  g_gate);
    cudaGetSymbolAddress((void**)&uu,  g_up);
    cudaGetSymbolAddress((void**)&memr, g_memr);
    cudaGetSymbolAddress((void**)&wq,  g_wq);
    cudaGetSymbolAddress((void**)&wk,  g_wk);
    cudaGetSymbolAddress((void**)&wv,  g_wv);
    cudaGetSymbolAddress((void**)&wo,  g_wo);
    cudaGetSymbolAddress((void**)&gw,  g_gw);
    cudaGetSymbolAddress((void**)&uw,  g_uw);
    cudaGetSymbolAddress((void**)&dw,  g_dw);

    // tf32-round GEMM B operands (weights) + memory activation
    round_pass(Wq, wq, (size_t)HID * HID);
    round_pass(Wk, wk, (size_t)HID * HID);
    round_pass(Wv, wv, (size_t)HID * HID);
    round_pass(Wo, wo, (size_t)HID * HID);
    round_pass(gatew, gw, (size_t)DFF * HID);
    round_pass(upw,   uw, (size_t)DFF * HID);
    round_pass(downw, dw, (size_t)HID * DFF);
    round_pass(mem, memr, (size_t)NTOK * HID);

    // 1. ln1 (tf32-rounded output)
    layernorm_k<<<NTOK, 256>>>(hid, ln1w, ln1b, xln);

    // 2-4. Q/K/V projections (tensor-core tf32 GEMMs)
    dim3 gsq(HID / GN, NTOK / GM);
    gemm_mma<<<gsq, 256>>>(xln,  wq, nullptr, q, NTOK, HID, HID);
    gemm_mma<<<gsq, 256>>>(memr, wk, nullptr, k, NTOK, HID, HID);
    gemm_mma<<<gsq, 256>>>(memr, wv, nullptr, v, NTOK, HID, HID);

    // 5. RoPE (in place)
    const int rope_threads = NTOK * NHEAD * 8;
    rope_k<<<(rope_threads + 255) / 256, 256>>>(q, k, pos);

    // 6. Attention -> ctx (tf32-rounded)
    dim3 ga(SEQ / 64, NHEAD, BATCH);
    attn_k<<<ga, 256>>>(q, k, v, mask, ctx);

    // 7. O projection + residual
    gemm_mma<<<gsq, 256>>>(ctx, wo, hid, h, NTOK, HID, HID);

    // 8. ln2 (rounded)
    layernorm_k<<<NTOK, 256>>>(h, ln2w, ln2b, y);

    // 9-10. gate / up
    dim3 gff(DFF / GN, NTOK / GM);
    gemm_mma<<<gff, 256>>>(y, gw, nullptr, gg, NTOK, DFF, HID);
    gemm_mma<<<gff, 256>>>(y, uw, nullptr, uu, NTOK, DFF, HID);

    // 11. silu(gate) * up  (in place into gg, rounded)
    const int n4 = (NTOK * DFF) / 4;
    silu_mul_k<<<(n4 + 255) / 256, 256>>>(gg, uu, n4);

    // 12. down projection + residual -> out
    gemm_mma<<<gsq, 256>>>(gg, dw, h, out, NTOK, HID, DFF);
}